// round 7
// baseline (speedup 1.0000x reference)
#include <cuda_runtime.h>
#include <float.h>

// TropicalLinear: out[n,o] = bias[o] + max_k( x[n,k] + w[o,k] )
// N=128, IN=1024, OUT=1024, fp32.  (soft - stop_grad(soft) == 0 exactly)
//
// Exact candidate pruning; fused single kernel, 256 CTAs x 512 thr, 2/SM:
//   prefetch: x row + bias + row-max reduction  (hidden under stage A)
//   stage A : transpose w -> wT (2 tiles in flight) + per-CTA w min/max
//   grid barrier (nanosleep-backoff spin)
//   stage B : w spread -> threshold -> compact candidates -> one MLP-4
//             gather-max wave over L2-hot wT rows -> +bias -> store.

#define N_ROWS  128
#define IN_DIM  1024
#define OUT_DIM 1024
#define NCTAS   256
#define THREADS 512

__device__ float  g_wT[IN_DIM * OUT_DIM];   // wT[k][o] = w[o][k]  (4 MB)
__device__ float2 g_wrng[NCTAS];            // per-CTA (min, max) of w
__device__ unsigned g_arrive;               // zero-init; reset each run
__device__ unsigned g_depart;               // zero-init; reset each run

__global__ __launch_bounds__(THREADS, 2)
void tropical_fused(const float* __restrict__ x, const float* __restrict__ w,
                    const float* __restrict__ bias, float* __restrict__ out)
{
    __shared__ float tile[2][32][33];        // two transpose tiles in flight
    __shared__ float s_xm[16], s_mn[16], s_mx[16];
    __shared__ float s_thr;
    __shared__ int   s_cnt;
    __shared__ int   s_ck[IN_DIM + 16];
    __shared__ float s_cx[IN_DIM + 16];

    const int b    = blockIdx.x;             // 0..255
    const int t    = threadIdx.x;
    const int lane = t & 31;
    const int wp   = t >> 5;                 // 0..15

    const int n    = b >> 1;                 // row 0..127
    const int half = b & 1;                  // o-half
    const int col  = half * 128 + (t >> 2);  // global float4 column
    const int q    = t & 3;                  // candidate quarter

    // ================= prefetch (independent of stage A) ============
    const float2 xv2 = __ldg(&((const float2*)x)[(size_t)n * 512 + t]);
    const float4 bv  = __ldg(&((const float4*)bias)[col]);
    {
        float xm = fmaxf(xv2.x, xv2.y);
        #pragma unroll
        for (int d = 16; d; d >>= 1)
            xm = fmaxf(xm, __shfl_xor_sync(0xffffffffu, xm, d));
        if (lane == 0) s_xm[wp] = xm;        // consumed after barrier
    }

    // ================= stage A: transpose + w range =================
    float wmn =  FLT_MAX;
    float wmx = -FLT_MAX;
    {
        const int g   = wp >> 3;             // warp group 0/1 -> own tile
        const int wpl = wp & 7;
        #pragma unroll 1
        for (int it = 0; it < 2; it++) {
            const int tile_id = b * 4 + it * 2 + g;   // 0..1023
            const int tr = tile_id >> 5;              // k-tile
            const int tc = tile_id & 31;              // o-tile
            #pragma unroll
            for (int r = wpl; r < 32; r += 8) {
                float v = __ldg(&w[(size_t)(tc * 32 + r) * IN_DIM + tr * 32 + lane]);
                wmn = fminf(wmn, v);
                wmx = fmaxf(wmx, v);
                tile[g][r][lane] = v;
            }
            __syncthreads();
            #pragma unroll
            for (int r = wpl; r < 32; r += 8)
                g_wT[(size_t)(tr * 32 + r) * OUT_DIM + tc * 32 + lane] =
                    tile[g][lane][r];
            __syncthreads();
        }
    }
    #pragma unroll
    for (int d = 16; d; d >>= 1) {
        wmn = fminf(wmn, __shfl_xor_sync(0xffffffffu, wmn, d));
        wmx = fmaxf(wmx, __shfl_xor_sync(0xffffffffu, wmx, d));
    }
    if (lane == 0) { s_mn[wp] = wmn; s_mx[wp] = wmx; }
    __syncthreads();
    if (t == 0) {
        float mn = s_mn[0], mx = s_mx[0];
        #pragma unroll
        for (int i = 1; i < 16; i++) {
            mn = fminf(mn, s_mn[i]);
            mx = fmaxf(mx, s_mx[i]);
        }
        g_wrng[b] = make_float2(mn, mx);
    }

    // ================= grid barrier (backoff spin) ==================
    __syncthreads();
    __threadfence();
    if (t == 0) {
        atomicAdd(&g_arrive, 1u);
        while (*(volatile unsigned*)&g_arrive < NCTAS) __nanosleep(64);
    }
    __syncthreads();
    __threadfence();

    // ================= stage B: threshold + compact + gather ========
    {
        float rmn = FLT_MAX, rmx = -FLT_MAX;
        if (t < NCTAS) {
            float2 rr = g_wrng[t];
            rmn = rr.x; rmx = rr.y;
        }
        #pragma unroll
        for (int d = 16; d; d >>= 1) {
            rmn = fminf(rmn, __shfl_xor_sync(0xffffffffu, rmn, d));
            rmx = fmaxf(rmx, __shfl_xor_sync(0xffffffffu, rmx, d));
        }
        if (lane == 0 && wp < 8) { s_mn[wp] = rmn; s_mx[wp] = rmx; }
    }
    __syncthreads();

    if (t == 0) {
        float m = s_xm[0];
        #pragma unroll
        for (int i = 1; i < 16; i++) m = fmaxf(m, s_xm[i]);
        float mn = s_mn[0], mx = s_mx[0];
        #pragma unroll
        for (int i = 1; i < 8; i++) {
            mn = fminf(mn, s_mn[i]);
            mx = fmaxf(mx, s_mx[i]);
        }
        float slack = 1e-5f + 1e-6f * (fabsf(m) + fmaxf(fabsf(mx), fabsf(mn)));
        s_thr = m - (mx - mn) - slack;
        s_cnt = 0;
    }
    __syncthreads();

    // compact candidates (thread owns k = 2t, 2t+1)
    {
        const float thr = s_thr;
        if (xv2.x >= thr) {
            int p = atomicAdd(&s_cnt, 1);
            s_ck[p] = 2 * t;
            s_cx[p] = xv2.x;
        }
        if (xv2.y >= thr) {
            int p = atomicAdd(&s_cnt, 1);
            s_ck[p] = 2 * t + 1;
            s_cx[p] = xv2.y;
        }
    }
    __syncthreads();
    const int cnt  = s_cnt;                  // >= 1 (row max qualifies)
    const int cntp = (cnt + 15) & ~15;
    if (t < cntp - cnt) {                    // pad with candidate 0 (idempotent)
        s_ck[cnt + t] = s_ck[0];
        s_cx[cnt + t] = s_cx[0];
    }
    __syncthreads();

    // gather: 4 threads per float4 output, quarter-split candidates,
    // 4 independent LDG.128 per batch of 16 candidates.
    const float4* wt4 = (const float4*)g_wT; // [IN_DIM][OUT_DIM/4]
    float4 acc = make_float4(-FLT_MAX, -FLT_MAX, -FLT_MAX, -FLT_MAX);

    for (int c0 = q; c0 < cntp; c0 += 16) {
        const int   k0 = s_ck[c0],      k1 = s_ck[c0 + 4];
        const int   k2 = s_ck[c0 + 8],  k3 = s_ck[c0 + 12];
        const float x0 = s_cx[c0],      x1 = s_cx[c0 + 4];
        const float x2 = s_cx[c0 + 8],  x3 = s_cx[c0 + 12];
        float4 w0 = wt4[(size_t)k0 * (OUT_DIM / 4) + col];
        float4 w1 = wt4[(size_t)k1 * (OUT_DIM / 4) + col];
        float4 w2 = wt4[(size_t)k2 * (OUT_DIM / 4) + col];
        float4 w3 = wt4[(size_t)k3 * (OUT_DIM / 4) + col];
        acc.x = fmaxf(acc.x, x0 + w0.x); acc.y = fmaxf(acc.y, x0 + w0.y);
        acc.z = fmaxf(acc.z, x0 + w0.z); acc.w = fmaxf(acc.w, x0 + w0.w);
        acc.x = fmaxf(acc.x, x1 + w1.x); acc.y = fmaxf(acc.y, x1 + w1.y);
        acc.z = fmaxf(acc.z, x1 + w1.z); acc.w = fmaxf(acc.w, x1 + w1.w);
        acc.x = fmaxf(acc.x, x2 + w2.x); acc.y = fmaxf(acc.y, x2 + w2.y);
        acc.z = fmaxf(acc.z, x2 + w2.z); acc.w = fmaxf(acc.w, x2 + w2.w);
        acc.x = fmaxf(acc.x, x3 + w3.x); acc.y = fmaxf(acc.y, x3 + w3.y);
        acc.z = fmaxf(acc.z, x3 + w3.z); acc.w = fmaxf(acc.w, x3 + w3.w);
    }

    // combine the 4 quarter partials (quads are warp-aligned)
    #pragma unroll
    for (int d = 1; d < 4; d <<= 1) {
        acc.x = fmaxf(acc.x, __shfl_xor_sync(0xffffffffu, acc.x, d));
        acc.y = fmaxf(acc.y, __shfl_xor_sync(0xffffffffu, acc.y, d));
        acc.z = fmaxf(acc.z, __shfl_xor_sync(0xffffffffu, acc.z, d));
        acc.w = fmaxf(acc.w, __shfl_xor_sync(0xffffffffu, acc.w, d));
    }

    if (q == 0) {
        acc.x += bv.x; acc.y += bv.y; acc.z += bv.z; acc.w += bv.w;
        ((float4*)out)[(size_t)n * (OUT_DIM / 4) + col] = acc;
    }

    // ---- counter reset (last departing CTA resets both) ----
    __syncthreads();
    if (t == 0) {
        unsigned d = atomicAdd(&g_depart, 1u);
        if (d == NCTAS - 1) {
            g_arrive = 0;
            __threadfence();
            g_depart = 0;
        }
    }
}

extern "C" void kernel_launch(void* const* d_in, const int* in_sizes, int n_in,
                              void* d_out, int out_size)
{
    const float* x    = (const float*)d_in[0];   // [128, 1024]
    const float* w    = (const float*)d_in[1];   // [1024, 1024]
    const float* bias = (const float*)d_in[2];   // [1024]
    float* out = (float*)d_out;                  // [128, 1024]

    tropical_fused<<<NCTAS, THREADS>>>(x, w, bias, out);
}

// round 8
// speedup vs baseline: 1.0194x; 1.0194x over previous
#include <cuda_runtime.h>
#include <float.h>

// TropicalLinear: out[n,o] = bias[o] + max_k( x[n,k] + w[o,k] )
// N=128, IN=1024, OUT=1024, fp32.  (soft - stop_grad(soft) == 0 exactly)
//
// No transpose, no grid barrier:
//   K0: per row n: M_n = max x, compact candidates {k : x >= M_n - B - eps}
//       into global list (order-irrelevant: max over identical value set).
//   K2: warp owns output column o. Loads w[o][:] coalesced into smem
//       (w read exactly once, 4 MB total), computes spread_o = max-min.
//       If spread_o <= B (guaranteed proof: winner k needs
//       x[n,k] >= M_n - spread_o), candidate list is a superset of
//       possible winners -> gather-max over ~13 smem entries per output.
//       Else (adversarial input only): exact full-K fallback.

#define N_ROWS  128
#define IN_DIM  1024
#define OUT_DIM 1024
#define B_EXCL  1.05f            // >= spread of uniform(-0.5,0.5) always
#define CAND_CAP IN_DIM          // per-row global capacity (always enough)
#define SMEM_CAND 64             // candidates staged in smem per row

__device__ float2 g_cand[N_ROWS * CAND_CAP];  // (.x = k bits, .y = x val)
__device__ int    g_cnt[N_ROWS];

// ---------------------------------------------------------------- K0
__global__ __launch_bounds__(256)
void k0_candidates(const float* __restrict__ x)
{
    const int n    = blockIdx.x;
    const int t    = threadIdx.x;
    const int lane = t & 31;
    const int wp   = t >> 5;

    __shared__ float s_xm[8];
    __shared__ float s_thr;
    __shared__ int   s_cnt;

    const float4 xv = __ldg(&((const float4*)x)[(size_t)n * (IN_DIM / 4) + t]);
    float xm = fmaxf(fmaxf(xv.x, xv.y), fmaxf(xv.z, xv.w));
    #pragma unroll
    for (int d = 16; d; d >>= 1)
        xm = fmaxf(xm, __shfl_xor_sync(0xffffffffu, xm, d));
    if (lane == 0) s_xm[wp] = xm;
    __syncthreads();
    if (t == 0) {
        float m = s_xm[0];
        #pragma unroll
        for (int i = 1; i < 8; i++) m = fmaxf(m, s_xm[i]);
        s_thr = m - B_EXCL - 1e-5f;   // 1e-5 >> fp32 sum-rounding at |v|~5
        s_cnt = 0;
    }
    __syncthreads();

    const float thr = s_thr;
    float v[4] = {xv.x, xv.y, xv.z, xv.w};
    #pragma unroll
    for (int j = 0; j < 4; j++) {
        if (v[j] >= thr) {
            int p = atomicAdd(&s_cnt, 1);
            g_cand[(size_t)n * CAND_CAP + p] =
                make_float2(__int_as_float(t * 4 + j), v[j]);
        }
    }
    __syncthreads();
    if (t == 0) g_cnt[n] = s_cnt;
}

// ---------------------------------------------------------------- K2
__global__ __launch_bounds__(256, 2)
void k2_gather(const float* __restrict__ x, const float* __restrict__ w,
               const float* __restrict__ bias, float* __restrict__ out)
{
    __shared__ float  w_s[8 * IN_DIM];        // 8 o-rows, 32 KB
    __shared__ float2 s_cand[32 * (SMEM_CAND + 1)];  // padded stride 65
    __shared__ int    s_cnt_sh[32];

    const int b    = blockIdx.x;              // 0..255
    const int t    = threadIdx.x;
    const int lane = t & 31;
    const int wp   = t >> 5;                  // 0..7

    const int o  = (b & 127) * 8 + wp;        // this warp's output column
    const int n0 = (b >> 7) * 64;             // n-half

    // ---- load w[o][:] coalesced (MLP=8), min/max on the fly ----
    float wmn =  FLT_MAX;
    float wmx = -FLT_MAX;
    {
        const float4* wr = (const float4*)(w + (size_t)o * IN_DIM);
        float4* ws4 = (float4*)(w_s + wp * IN_DIM);
        #pragma unroll
        for (int j = 0; j < 8; j++) {
            float4 v = __ldg(wr + lane + 32 * j);
            wmn = fminf(wmn, fminf(fminf(v.x, v.y), fminf(v.z, v.w)));
            wmx = fmaxf(wmx, fmaxf(fmaxf(v.x, v.y), fmaxf(v.z, v.w)));
            ws4[lane + 32 * j] = v;
        }
    }
    #pragma unroll
    for (int d = 16; d; d >>= 1) {
        wmn = fminf(wmn, __shfl_xor_sync(0xffffffffu, wmn, d));
        wmx = fmaxf(wmx, __shfl_xor_sync(0xffffffffu, wmx, d));
    }
    const bool ok = (wmx - wmn) <= B_EXCL;    // candidate list valid for this o
    const float bo = __ldg(bias + o);
    const float* wrow = w_s + wp * IN_DIM;
    __syncwarp();                             // own warp's w_s visible

    #pragma unroll 1
    for (int q = 0; q < 2; q++) {
        const int nb = n0 + q * 32;

        __syncthreads();                      // s_cand reuse safe
        // stage first 64 candidates of 32 rows (coalesced, L2-hot)
        #pragma unroll
        for (int e = t; e < 32 * SMEM_CAND; e += 256) {
            const int r = e >> 6, c = e & 63;
            s_cand[r * (SMEM_CAND + 1) + c] =
                g_cand[(size_t)(nb + r) * CAND_CAP + c];
        }
        if (t < 32) s_cnt_sh[t] = g_cnt[nb + t];
        __syncthreads();

        const int n   = nb + lane;
        const int cnt = s_cnt_sh[lane];
        float acc = -FLT_MAX;

        if (ok) {
            const float2* my = s_cand + lane * (SMEM_CAND + 1);
            const int clim = min(cnt, SMEM_CAND);
            int c = 0;
            #pragma unroll 4
            for (; c < clim; c++) {
                float2 kx = my[c];
                acc = fmaxf(acc, kx.y + wrow[__float_as_int(kx.x)]);
            }
            for (; c < cnt; c++) {            // rare overflow tail (L2)
                float2 kx = __ldg(&g_cand[(size_t)n * CAND_CAP + c]);
                acc = fmaxf(acc, kx.y + wrow[__float_as_int(kx.x)]);
            }
        } else {
            // exact fallback (adversarial inputs only): full K loop
            const float* xr = x + (size_t)n * IN_DIM;
            for (int k = 0; k < IN_DIM; k++)
                acc = fmaxf(acc, __ldg(xr + k) + wrow[k]);
        }

        out[(size_t)n * OUT_DIM + o] = acc + bo;
    }
}

extern "C" void kernel_launch(void* const* d_in, const int* in_sizes, int n_in,
                              void* d_out, int out_size)
{
    const float* x    = (const float*)d_in[0];   // [128, 1024]
    const float* w    = (const float*)d_in[1];   // [1024, 1024]
    const float* bias = (const float*)d_in[2];   // [1024]
    float* out = (float*)d_out;                  // [128, 1024]

    k0_candidates<<<N_ROWS, 256>>>(x);
    k2_gather<<<256, 256>>>(x, w, bias, out);
}